// round 2
// baseline (speedup 1.0000x reference)
#include <cuda_runtime.h>
#include <cuda_bf16.h>
#include <math.h>

// ---------------------------------------------------------------------------
// Problem constants
//   BATCH=4 SEQ=4096 DIM=1024 HEADS=8 DIM_HEAD=64 WS=128
//   windows w = 32, context jlen = 384
// ---------------------------------------------------------------------------
#define BATCH 4
#define SEQ   4096
#define DIM   1024
#define HEADS 8
#define DH    64
#define WS    128
#define NWIN  32
#define INNER 512          // HEADS*DH
#define JLEN  384
#define M_ROWS (BATCH * SEQ)   // 16384

#define NEG_INF (-3.402823466e+38f)

// ---------------------------------------------------------------------------
// Scratch (device globals: no allocation allowed in kernel_launch).
// Kernels reference these directly -- kernel_launch makes NO runtime API
// calls other than kernel launches (maximally capture-safe).
// ---------------------------------------------------------------------------
__device__ float g_xn  [M_ROWS * DIM];     // layernormed x       (67 MB)
__device__ float g_qkv [M_ROWS * DIM];     // qkv = xn @ Wqkv^T   (67 MB)
__device__ float g_attn[M_ROWS * INNER];   // attention output    (33 MB)
__device__ float g_kcos[JLEN * DH];
__device__ float g_ksin[JLEN * DH];
__device__ float g_qcs [WS * DH];          // cos*scale*dh^-0.5 for q
__device__ float g_qsn [WS * DH];          // sin*scale*dh^-0.5 for q

// ---------------------------------------------------------------------------
// Rotary / xpos coefficient precompute (tiny, runs each replay)
// ---------------------------------------------------------------------------
__global__ void rope_precompute_kernel() {
    int idx = blockIdx.x * blockDim.x + threadIdx.x;
    if (idx >= JLEN * DH) return;
    int t = idx / DH;
    int e = idx % DH;
    int f = e & 31;                        // freqs/scale duplicated across halves
    float invf = powf(10000.0f, -(2.0f * (float)f) / (float)DH);
    float ang  = (float)t * invf;
    float sb   = (2.0f * (float)f + 0.4f * (float)DH) / (1.4f * (float)DH);
    float pw   = ((float)t - (float)(JLEN / 2)) / (float)(WS / 2);
    float sc   = powf(sb, pw);
    float c = cosf(ang), s = sinf(ang);
    g_kcos[idx] = c / sc;                  // k uses inverse scale
    g_ksin[idx] = s / sc;
    if (t >= JLEN - WS) {                  // q uses last WS rows, scale, *dh^-0.5
        int i = t - (JLEN - WS);
        g_qcs[i * DH + e] = c * sc * 0.125f;
        g_qsn[i * DH + e] = s * sc * 0.125f;
    }
}

// ---------------------------------------------------------------------------
// LayerNorm: one block per row of 1024. Writes g_xn.
// ---------------------------------------------------------------------------
__global__ void __launch_bounds__(256) ln_kernel(const float* __restrict__ x,
                                                 const float* __restrict__ gam,
                                                 const float* __restrict__ bet) {
    __shared__ float red [8];
    __shared__ float red2[8];
    __shared__ float s_mu, s_rstd;
    int row = blockIdx.x;
    int t = threadIdx.x;
    float4 v = ((const float4*)(x + (size_t)row * DIM))[t];
    float s  = v.x + v.y + v.z + v.w;
    float sq = v.x * v.x + v.y * v.y + v.z * v.z + v.w * v.w;
    #pragma unroll
    for (int o = 16; o > 0; o >>= 1) {
        s  += __shfl_xor_sync(0xffffffffu, s,  o);
        sq += __shfl_xor_sync(0xffffffffu, sq, o);
    }
    if ((t & 31) == 0) { red[t >> 5] = s; red2[t >> 5] = sq; }
    __syncthreads();
    if (t < 32) {
        float ss = (t < 8) ? red [t] : 0.0f;
        float qq = (t < 8) ? red2[t] : 0.0f;
        #pragma unroll
        for (int o = 4; o > 0; o >>= 1) {
            ss += __shfl_xor_sync(0xffffffffu, ss, o);
            qq += __shfl_xor_sync(0xffffffffu, qq, o);
        }
        if (t == 0) {
            float mu  = ss * (1.0f / DIM);
            float var = qq * (1.0f / DIM) - mu * mu;
            s_mu = mu;
            s_rstd = rsqrtf(var + 1e-5f);
        }
    }
    __syncthreads();
    float mu = s_mu, rstd = s_rstd;
    float4 gg = ((const float4*)gam)[t];
    float4 bb = ((const float4*)bet)[t];
    float4 o4;
    o4.x = (v.x - mu) * rstd * gg.x + bb.x;
    o4.y = (v.y - mu) * rstd * gg.y + bb.y;
    o4.z = (v.z - mu) * rstd * gg.z + bb.z;
    o4.w = (v.w - mu) * rstd * gg.w + bb.w;
    ((float4*)(g_xn + (size_t)row * DIM))[t] = o4;
}

// ---------------------------------------------------------------------------
// SGEMM (NT): C[M,N] = A[M,K] * B[N,K]^T, row-major, M,N %128==0, K %32==0.
// 128x128 tile, BK=32, 256 threads, 8x8 register blocking.
// which==0: A=g_xn,   C=g_qkv  (qkv projection,  N=1024, K=1024)
// which==1: A=g_attn, C=Cext   (out projection,  N=1024, K=512)
// ---------------------------------------------------------------------------
__global__ void __launch_bounds__(256) sgemm_nt(const float* __restrict__ B,
                                                float* __restrict__ Cext,
                                                int N, int K, int which) {
    const float* __restrict__ A = (which == 0) ? g_xn : g_attn;
    float* __restrict__ C       = (which == 0) ? g_qkv : Cext;

    __shared__ float As[32][128];
    __shared__ float Bs[32][128];
    const int t  = threadIdx.x;
    const int bm = blockIdx.y * 128;
    const int bn = blockIdx.x * 128;
    const int lr = t >> 3;          // 0..31
    const int lk = (t & 7) << 2;    // 0..28 step 4
    const int tx = t & 15;
    const int ty = t >> 4;

    float acc[8][8];
    #pragma unroll
    for (int i = 0; i < 8; i++)
        #pragma unroll
        for (int j = 0; j < 8; j++) acc[i][j] = 0.0f;

    for (int k0 = 0; k0 < K; k0 += 32) {
        #pragma unroll
        for (int p = 0; p < 4; p++) {
            int row = lr + 32 * p;
            float4 av = *(const float4*)&A[(size_t)(bm + row) * K + k0 + lk];
            As[lk + 0][row] = av.x;
            As[lk + 1][row] = av.y;
            As[lk + 2][row] = av.z;
            As[lk + 3][row] = av.w;
            float4 bv = *(const float4*)&B[(size_t)(bn + row) * K + k0 + lk];
            Bs[lk + 0][row] = bv.x;
            Bs[lk + 1][row] = bv.y;
            Bs[lk + 2][row] = bv.z;
            Bs[lk + 3][row] = bv.w;
        }
        __syncthreads();
        #pragma unroll
        for (int kk = 0; kk < 32; kk++) {
            float a[8], b[8];
            *(float4*)&a[0] = *(const float4*)&As[kk][ty * 8];
            *(float4*)&a[4] = *(const float4*)&As[kk][ty * 8 + 4];
            *(float4*)&b[0] = *(const float4*)&Bs[kk][tx * 8];
            *(float4*)&b[4] = *(const float4*)&Bs[kk][tx * 8 + 4];
            #pragma unroll
            for (int i = 0; i < 8; i++)
                #pragma unroll
                for (int j = 0; j < 8; j++)
                    acc[i][j] = fmaf(a[i], b[j], acc[i][j]);
        }
        __syncthreads();
    }
    #pragma unroll
    for (int i = 0; i < 8; i++) {
        float* crow = &C[(size_t)(bm + ty * 8 + i) * N + bn + tx * 8];
        float4 v0 = make_float4(acc[i][0], acc[i][1], acc[i][2], acc[i][3]);
        float4 v1 = make_float4(acc[i][4], acc[i][5], acc[i][6], acc[i][7]);
        *(float4*)&crow[0] = v0;
        *(float4*)&crow[4] = v1;
    }
}

// ---------------------------------------------------------------------------
// Windowed attention. Grid (NWIN, BATCH*HEADS), 128 threads.
// Thread i owns q row i of window wi. Context = windows wi-1..wi+1, streamed
// as 64-row k/v subchunks (32 KB STATIC shared -- no attribute call needed).
// Mask reduces to i <= jc <= i+256 with jc = cc*128 + sub*64 + j.
// Online softmax with branch-rescale (rare path).
// ---------------------------------------------------------------------------
#define SUB 64

__global__ void __launch_bounds__(128) attn_kernel() {
    __shared__ float ks[SUB][DH];   // 16 KB
    __shared__ float vs[SUB][DH];   // 16 KB

    const float* __restrict__ qkv = g_qkv;
    const int wi = blockIdx.x;
    const int bh = blockIdx.y;
    const int b  = bh >> 3;
    const int h  = bh & 7;
    const int i  = threadIdx.x;

    // ---- load + rotate q (registers) ----
    const float* qrow = qkv + ((size_t)(b * SEQ + wi * WS + i) * DIM + h * DH);
    const float* qc = g_qcs + i * DH;
    const float* qs = g_qsn + i * DH;
    float qr[DH];
    #pragma unroll
    for (int e4 = 0; e4 < 8; e4++) {
        float4 x1 = ((const float4*)qrow)[e4];
        float4 x2 = ((const float4*)qrow)[e4 + 8];
        float4 c1 = ((const float4*)qc)[e4];
        float4 s1 = ((const float4*)qs)[e4];
        float4 c2 = ((const float4*)qc)[e4 + 8];
        float4 s2 = ((const float4*)qs)[e4 + 8];
        qr[e4 * 4 + 0] = x1.x * c1.x - x2.x * s1.x;
        qr[e4 * 4 + 1] = x1.y * c1.y - x2.y * s1.y;
        qr[e4 * 4 + 2] = x1.z * c1.z - x2.z * s1.z;
        qr[e4 * 4 + 3] = x1.w * c1.w - x2.w * s1.w;
        qr[e4 * 4 + 32 + 0] = x2.x * c2.x + x1.x * s2.x;
        qr[e4 * 4 + 32 + 1] = x2.y * c2.y + x1.y * s2.y;
        qr[e4 * 4 + 32 + 2] = x2.z * c2.z + x1.z * s2.z;
        qr[e4 * 4 + 32 + 3] = x2.w * c2.w + x1.w * s2.w;
    }

    float m = NEG_INF, l = 0.0f;
    float acc[DH];
    #pragma unroll
    for (int e = 0; e < DH; e++) acc[e] = 0.0f;

    for (int cc = 0; cc < 3; cc++) {
        int kw = wi - 1 + cc;
        if (kw < 0 || kw >= NWIN) continue;      // pad windows: fully masked

        for (int sub = 0; sub < 2; sub++) {
            // warp-uniform j bounds within this 64-row subchunk
            int jstart = (cc == 0) ? max(0, (i & ~31) - sub * SUB) : 0;
            int jend   = (cc == 2) ? min(SUB - 1, (i | 31) - sub * SUB) : (SUB - 1);
            // fully-dead subchunk for every warp? (cc==2, sub==1, low warps)
            // individual warps with jend<jstart just skip the j-loop below.

            // ---- cooperative coalesced load of k (raw) and v subchunk ----
            const float* kbase = qkv +
                ((size_t)(b * SEQ + kw * WS + sub * SUB) * DIM + h * DH);
            #pragma unroll
            for (int p = 0; p < 8; p++) {
                int r  = p * 8 + (i >> 4);
                int e4 = (i & 15);
                *(float4*)&ks[r][e4 * 4] =
                    *(const float4*)(kbase + (size_t)r * DIM + e4 * 4);
                *(float4*)&vs[r][e4 * 4] =
                    *(const float4*)(kbase + (size_t)r * DIM + INNER + e4 * 4);
            }
            __syncthreads();

            // ---- rotate k in place (conflict-free pair mapping) ----
            const float* kcb = g_kcos + (cc * WS + sub * SUB) * DH;
            const float* ksb = g_ksin + (cc * WS + sub * SUB) * DH;
            #pragma unroll
            for (int p = 0; p < 16; p++) {
                int idx = p * 128 + i;
                int r = idx >> 5;
                int e = idx & 31;
                float x1 = ks[r][e], x2 = ks[r][e + 32];
                float c1 = kcb[r * DH + e],      s1 = ksb[r * DH + e];
                float c2 = kcb[r * DH + e + 32], s2 = ksb[r * DH + e + 32];
                ks[r][e]      = x1 * c1 - x2 * s1;
                ks[r][e + 32] = x2 * c2 + x1 * s2;
            }
            __syncthreads();

            // per-lane valid j range
            int jlo = (cc == 0) ? (i - sub * SUB) : 0;       // clamp via compare
            int jhi = (cc == 2) ? (i - sub * SUB) : (SUB - 1);

            for (int j = jstart; j <= jend; j++) {
                float d0 = 0.0f, d1 = 0.0f, d2 = 0.0f, d3 = 0.0f;
                #pragma unroll
                for (int e4 = 0; e4 < 16; e4++) {
                    float4 k4 = *(const float4*)&ks[j][e4 * 4];
                    d0 = fmaf(qr[e4 * 4 + 0], k4.x, d0);
                    d1 = fmaf(qr[e4 * 4 + 1], k4.y, d1);
                    d2 = fmaf(qr[e4 * 4 + 2], k4.z, d2);
                    d3 = fmaf(qr[e4 * 4 + 3], k4.w, d3);
                }
                float sc = (d0 + d1) + (d2 + d3);
                if (j >= jlo && j <= jhi) {
                    if (sc > m) {
                        float corr = __expf(m - sc);   // m=-inf -> corr=0
                        m = sc;
                        l *= corr;
                        #pragma unroll
                        for (int e = 0; e < DH; e++) acc[e] *= corr;
                    }
                    float p = __expf(sc - m);
                    l += p;
                    #pragma unroll
                    for (int e4 = 0; e4 < 16; e4++) {
                        float4 v4 = *(const float4*)&vs[j][e4 * 4];
                        acc[e4 * 4 + 0] = fmaf(p, v4.x, acc[e4 * 4 + 0]);
                        acc[e4 * 4 + 1] = fmaf(p, v4.y, acc[e4 * 4 + 1]);
                        acc[e4 * 4 + 2] = fmaf(p, v4.z, acc[e4 * 4 + 2]);
                        acc[e4 * 4 + 3] = fmaf(p, v4.w, acc[e4 * 4 + 3]);
                    }
                }
            }
            __syncthreads();
        }
    }

    float inv_l = 1.0f / l;
    float* orow = g_attn + ((size_t)(b * SEQ + wi * WS + i) * INNER + h * DH);
    #pragma unroll
    for (int e4 = 0; e4 < 16; e4++) {
        float4 o4 = make_float4(acc[e4 * 4 + 0] * inv_l, acc[e4 * 4 + 1] * inv_l,
                                acc[e4 * 4 + 2] * inv_l, acc[e4 * 4 + 3] * inv_l);
        *(float4*)(orow + e4 * 4) = o4;
    }
}

// ---------------------------------------------------------------------------
// Launch: pure kernel launches, nothing else.
// ---------------------------------------------------------------------------
extern "C" void kernel_launch(void* const* d_in, const int* in_sizes, int n_in,
                              void* d_out, int out_size) {
    const float* x     = (const float*)d_in[0];
    const float* ln_g  = (const float*)d_in[1];
    const float* ln_b  = (const float*)d_in[2];
    const float* w_qkv = (const float*)d_in[3];
    const float* w_out = (const float*)d_in[4];
    float* out = (float*)d_out;

    // 1. rotary tables (independent)
    rope_precompute_kernel<<<(JLEN * DH + 255) / 256, 256>>>();

    // 2. layernorm -> g_xn
    ln_kernel<<<M_ROWS, 256>>>(x, ln_g, ln_b);

    // 3. qkv = xn @ w_qkv^T   (M=16384, N=1024, K=1024) -> g_qkv
    sgemm_nt<<<dim3(DIM / 128, M_ROWS / 128), 256>>>(w_qkv, nullptr, DIM, DIM, 0);

    // 4. windowed attention -> g_attn
    attn_kernel<<<dim3(NWIN, BATCH * HEADS), 128>>>();

    // 5. out = attn @ w_out^T (M=16384, N=1024, K=512) -> d_out
    sgemm_nt<<<dim3(DIM / 128, M_ROWS / 128), 256>>>(w_out, out, DIM, INNER, 1);
}

// round 6
// speedup vs baseline: 1.8039x; 1.8039x over previous
#include <cuda_runtime.h>
#include <cuda_bf16.h>
#include <math.h>
#include <stdint.h>

// ---------------------------------------------------------------------------
// Problem constants
// ---------------------------------------------------------------------------
#define BATCH 4
#define SEQ   4096
#define DIM   1024
#define HEADS 8
#define DH    64
#define WS    128
#define NWIN  32
#define INNER 512
#define JLEN  384
#define M_ROWS (BATCH * SEQ)   // 16384

#define NEG_INF (-3.402823466e+38f)

// ---------------------------------------------------------------------------
// Scratch (device globals; kernel_launch makes NO runtime API calls)
// ---------------------------------------------------------------------------
__device__ float g_xn  [M_ROWS * DIM];
__device__ float g_qkv [M_ROWS * DIM];
__device__ float g_attn[M_ROWS * INNER];
__device__ float g_kcos[JLEN * DH];
__device__ float g_ksin[JLEN * DH];
__device__ float g_qcs [WS * DH];
__device__ float g_qsn [WS * DH];

// ---------------------------------------------------------------------------
// Helpers
// ---------------------------------------------------------------------------
__device__ __forceinline__ float f2tf32(float x) {
    uint32_t y;
    asm("cvt.rna.tf32.f32 %0, %1;" : "=r"(y) : "f"(x));
    return __uint_as_float(y);
}

__device__ __forceinline__ void mma_tf32(float* d,
                                         uint32_t a0, uint32_t a1,
                                         uint32_t a2, uint32_t a3,
                                         uint32_t b0, uint32_t b1) {
    asm volatile(
        "mma.sync.aligned.m16n8k8.row.col.f32.tf32.tf32.f32 "
        "{%0,%1,%2,%3}, {%4,%5,%6,%7}, {%8,%9}, {%0,%1,%2,%3};\n"
        : "+f"(d[0]), "+f"(d[1]), "+f"(d[2]), "+f"(d[3])
        : "r"(a0), "r"(a1), "r"(a2), "r"(a3), "r"(b0), "r"(b1));
}

// ---------------------------------------------------------------------------
// Rotary / xpos coefficient precompute
// ---------------------------------------------------------------------------
__global__ void rope_precompute_kernel() {
    int idx = blockIdx.x * blockDim.x + threadIdx.x;
    if (idx >= JLEN * DH) return;
    int t = idx / DH;
    int e = idx % DH;
    int f = e & 31;
    float invf = powf(10000.0f, -(2.0f * (float)f) / (float)DH);
    float ang  = (float)t * invf;
    float sb   = (2.0f * (float)f + 0.4f * (float)DH) / (1.4f * (float)DH);
    float pw   = ((float)t - (float)(JLEN / 2)) / (float)(WS / 2);
    float sc   = powf(sb, pw);
    float c = cosf(ang), s = sinf(ang);
    g_kcos[idx] = c / sc;
    g_ksin[idx] = s / sc;
    if (t >= JLEN - WS) {
        int i = t - (JLEN - WS);
        g_qcs[i * DH + e] = c * sc * 0.125f;
        g_qsn[i * DH + e] = s * sc * 0.125f;
    }
}

// ---------------------------------------------------------------------------
// LayerNorm
// ---------------------------------------------------------------------------
__global__ void __launch_bounds__(256) ln_kernel(const float* __restrict__ x,
                                                 const float* __restrict__ gam,
                                                 const float* __restrict__ bet) {
    __shared__ float red [8];
    __shared__ float red2[8];
    __shared__ float s_mu, s_rstd;
    int row = blockIdx.x;
    int t = threadIdx.x;
    float4 v = ((const float4*)(x + (size_t)row * DIM))[t];
    float s  = v.x + v.y + v.z + v.w;
    float sq = v.x * v.x + v.y * v.y + v.z * v.z + v.w * v.w;
    #pragma unroll
    for (int o = 16; o > 0; o >>= 1) {
        s  += __shfl_xor_sync(0xffffffffu, s,  o);
        sq += __shfl_xor_sync(0xffffffffu, sq, o);
    }
    if ((t & 31) == 0) { red[t >> 5] = s; red2[t >> 5] = sq; }
    __syncthreads();
    if (t < 32) {
        float ss = (t < 8) ? red [t] : 0.0f;
        float qq = (t < 8) ? red2[t] : 0.0f;
        #pragma unroll
        for (int o = 4; o > 0; o >>= 1) {
            ss += __shfl_xor_sync(0xffffffffu, ss, o);
            qq += __shfl_xor_sync(0xffffffffu, qq, o);
        }
        if (t == 0) {
            float mu  = ss * (1.0f / DIM);
            float var = qq * (1.0f / DIM) - mu * mu;
            s_mu = mu;
            s_rstd = rsqrtf(var + 1e-5f);
        }
    }
    __syncthreads();
    float mu = s_mu, rstd = s_rstd;
    float4 gg = ((const float4*)gam)[t];
    float4 bb = ((const float4*)bet)[t];
    float4 o4;
    o4.x = (v.x - mu) * rstd * gg.x + bb.x;
    o4.y = (v.y - mu) * rstd * gg.y + bb.y;
    o4.z = (v.z - mu) * rstd * gg.z + bb.z;
    o4.w = (v.w - mu) * rstd * gg.w + bb.w;
    ((float4*)(g_xn + (size_t)row * DIM))[t] = o4;
}

// ---------------------------------------------------------------------------
// TF32 mma.sync GEMM (NT): C[M,1024] = A[M,K] * B[1024,K]^T  (sm_80+ path,
// compiles for compute_100; runs on tensor cores as HMMA.TF32).
// CTA 128x128, BK=32, 256 thr = 8 warps (4m x 2n), warp tile 32x64.
// SMEM uses permuted-k layout k' = (k&3)*8 + (k>>2), row stride 36 words:
// every thread's m16n8k8 fragment words for all 4 k-steps are one contiguous
// 32B run -> 2x LDS.128 per fragment row, conflict-free.
// which==0: A=g_xn,   C=g_qkv  (K=1024)
// which==1: A=g_attn, C=Cext   (K=512)
// ---------------------------------------------------------------------------
#define SA 36          // padded row stride (words); 144B, 16B-aligned
#define NT_N 1024

__global__ void __launch_bounds__(256) gemm_mma(const float* __restrict__ Bmat,
                                                float* __restrict__ Cext,
                                                int K, int which) {
    __shared__ float As[128 * SA];   // 18 KB
    __shared__ float Bs[128 * SA];   // 18 KB

    const float* __restrict__ A = which ? g_attn : g_xn;
    float* __restrict__ C       = which ? Cext : g_qkv;

    const int tid  = threadIdx.x;
    const int bn   = blockIdx.x * 128;
    const int bm   = blockIdx.y * 128;
    const int warp = tid >> 5;
    const int lane = tid & 31;
    const int wm   = warp & 3;          // 0..3 (m)
    const int wn   = warp >> 2;         // 0..1 (n)
    const int r    = lane >> 2;         // groupID 0..7
    const int c    = lane & 3;          // threadID_in_group
    const int r0   = tid >> 3;          // 0..31 (load row)
    const int u    = tid & 7;           // 0..7  (load k-quad)

    float acc[2][8][4];
    #pragma unroll
    for (int mt = 0; mt < 2; mt++)
        #pragma unroll
        for (int nt = 0; nt < 8; nt++)
            #pragma unroll
            for (int q = 0; q < 4; q++) acc[mt][nt][q] = 0.0f;

    const float* ag = A    + (size_t)(bm + r0) * K + u * 4;
    const float* bg = Bmat + (size_t)(bn + r0) * K + u * 4;

    float4 pa[4], pb[4];
    #pragma unroll
    for (int p = 0; p < 4; p++) {
        pa[p] = *(const float4*)(ag + (size_t)p * 32 * K);
        pb[p] = *(const float4*)(bg + (size_t)p * 32 * K);
    }

    for (int k0 = 0; k0 < K; k0 += 32) {
        // ---- store prefetched tile to smem (tf32-rounded, permuted k) ----
        #pragma unroll
        for (int p = 0; p < 4; p++) {
            int m = r0 + p * 32;
            As[m * SA +  0 + u] = f2tf32(pa[p].x);
            As[m * SA +  8 + u] = f2tf32(pa[p].y);
            As[m * SA + 16 + u] = f2tf32(pa[p].z);
            As[m * SA + 24 + u] = f2tf32(pa[p].w);
            Bs[m * SA +  0 + u] = f2tf32(pb[p].x);
            Bs[m * SA +  8 + u] = f2tf32(pb[p].y);
            Bs[m * SA + 16 + u] = f2tf32(pb[p].z);
            Bs[m * SA + 24 + u] = f2tf32(pb[p].w);
        }
        __syncthreads();

        // ---- prefetch next tile (latency hidden under compute) ----
        if (k0 + 32 < K) {
            #pragma unroll
            for (int p = 0; p < 4; p++) {
                pa[p] = *(const float4*)(ag + (size_t)(k0 + 32) + (size_t)p * 32 * K);
                pb[p] = *(const float4*)(bg + (size_t)(k0 + 32) + (size_t)p * 32 * K);
            }
        }

        // ---- fragments: A rows for this warp ----
        float aL[2][2][4], aH[2][2][4];
        #pragma unroll
        for (int mt = 0; mt < 2; mt++) {
            int rl = wm * 32 + mt * 16 + r;
            *(float4*)aL[mt][0] = *(const float4*)&As[rl * SA + c * 8];
            *(float4*)aL[mt][1] = *(const float4*)&As[rl * SA + c * 8 + 4];
            *(float4*)aH[mt][0] = *(const float4*)&As[(rl + 8) * SA + c * 8];
            *(float4*)aH[mt][1] = *(const float4*)&As[(rl + 8) * SA + c * 8 + 4];
        }

        #pragma unroll
        for (int nt = 0; nt < 8; nt++) {
            float bb[2][4];
            int nr = wn * 64 + nt * 8 + r;
            *(float4*)bb[0] = *(const float4*)&Bs[nr * SA + c * 8];
            *(float4*)bb[1] = *(const float4*)&Bs[nr * SA + c * 8 + 4];
            #pragma unroll
            for (int mt = 0; mt < 2; mt++) {
                #pragma unroll
                for (int s = 0; s < 4; s++) {
                    int q = s >> 1, o = (s & 1) * 2;
                    mma_tf32(acc[mt][nt],
                             __float_as_uint(aL[mt][q][o]),
                             __float_as_uint(aH[mt][q][o]),
                             __float_as_uint(aL[mt][q][o + 1]),
                             __float_as_uint(aH[mt][q][o + 1]),
                             __float_as_uint(bb[q][o]),
                             __float_as_uint(bb[q][o + 1]));
                }
            }
        }
        __syncthreads();
    }

    // ---- epilogue: c0/c1 adjacent cols -> float2 stores ----
    #pragma unroll
    for (int mt = 0; mt < 2; mt++) {
        #pragma unroll
        for (int nt = 0; nt < 8; nt++) {
            int row = bm + wm * 32 + mt * 16 + r;
            int col = bn + wn * 64 + nt * 8 + 2 * c;
            *(float2*)&C[(size_t)row * NT_N + col] =
                make_float2(acc[mt][nt][0], acc[mt][nt][1]);
            *(float2*)&C[(size_t)(row + 8) * NT_N + col] =
                make_float2(acc[mt][nt][2], acc[mt][nt][3]);
        }
    }
}

// ---------------------------------------------------------------------------
// Windowed attention (byte-identical to R2 passing version)
// ---------------------------------------------------------------------------
#define SUB 64

__global__ void __launch_bounds__(128) attn_kernel() {
    __shared__ float ks[SUB][DH];
    __shared__ float vs[SUB][DH];

    const float* __restrict__ qkv = g_qkv;
    const int wi = blockIdx.x;
    const int bh = blockIdx.y;
    const int b  = bh >> 3;
    const int h  = bh & 7;
    const int i  = threadIdx.x;

    const float* qrow = qkv + ((size_t)(b * SEQ + wi * WS + i) * DIM + h * DH);
    const float* qc = g_qcs + i * DH;
    const float* qs = g_qsn + i * DH;
    float qr[DH];
    #pragma unroll
    for (int e4 = 0; e4 < 8; e4++) {
        float4 x1 = ((const float4*)qrow)[e4];
        float4 x2 = ((const float4*)qrow)[e4 + 8];
        float4 c1 = ((const float4*)qc)[e4];
        float4 s1 = ((const float4*)qs)[e4];
        float4 c2 = ((const float4*)qc)[e4 + 8];
        float4 s2 = ((const float4*)qs)[e4 + 8];
        qr[e4 * 4 + 0] = x1.x * c1.x - x2.x * s1.x;
        qr[e4 * 4 + 1] = x1.y * c1.y - x2.y * s1.y;
        qr[e4 * 4 + 2] = x1.z * c1.z - x2.z * s1.z;
        qr[e4 * 4 + 3] = x1.w * c1.w - x2.w * s1.w;
        qr[e4 * 4 + 32 + 0] = x2.x * c2.x + x1.x * s2.x;
        qr[e4 * 4 + 32 + 1] = x2.y * c2.y + x1.y * s2.y;
        qr[e4 * 4 + 32 + 2] = x2.z * c2.z + x1.z * s2.z;
        qr[e4 * 4 + 32 + 3] = x2.w * c2.w + x1.w * s2.w;
    }

    float m = NEG_INF, l = 0.0f;
    float acc[DH];
    #pragma unroll
    for (int e = 0; e < DH; e++) acc[e] = 0.0f;

    for (int cc = 0; cc < 3; cc++) {
        int kw = wi - 1 + cc;
        if (kw < 0 || kw >= NWIN) continue;

        for (int sub = 0; sub < 2; sub++) {
            int jstart = (cc == 0) ? max(0, (i & ~31) - sub * SUB) : 0;
            int jend   = (cc == 2) ? min(SUB - 1, (i | 31) - sub * SUB) : (SUB - 1);

            const float* kbase = qkv +
                ((size_t)(b * SEQ + kw * WS + sub * SUB) * DIM + h * DH);
            #pragma unroll
            for (int p = 0; p < 8; p++) {
                int rr = p * 8 + (i >> 4);
                int e4 = (i & 15);
                *(float4*)&ks[rr][e4 * 4] =
                    *(const float4*)(kbase + (size_t)rr * DIM + e4 * 4);
                *(float4*)&vs[rr][e4 * 4] =
                    *(const float4*)(kbase + (size_t)rr * DIM + INNER + e4 * 4);
            }
            __syncthreads();

            const float* kcb = g_kcos + (cc * WS + sub * SUB) * DH;
            const float* ksb = g_ksin + (cc * WS + sub * SUB) * DH;
            #pragma unroll
            for (int p = 0; p < 16; p++) {
                int idx = p * 128 + i;
                int rr = idx >> 5;
                int e = idx & 31;
                float x1 = ks[rr][e], x2 = ks[rr][e + 32];
                float c1 = kcb[rr * DH + e],      s1 = ksb[rr * DH + e];
                float c2 = kcb[rr * DH + e + 32], s2 = ksb[rr * DH + e + 32];
                ks[rr][e]      = x1 * c1 - x2 * s1;
                ks[rr][e + 32] = x2 * c2 + x1 * s2;
            }
            __syncthreads();

            int jlo = (cc == 0) ? (i - sub * SUB) : 0;
            int jhi = (cc == 2) ? (i - sub * SUB) : (SUB - 1);

            for (int j = jstart; j <= jend; j++) {
                float d0 = 0.0f, d1 = 0.0f, d2 = 0.0f, d3 = 0.0f;
                #pragma unroll
                for (int e4 = 0; e4 < 16; e4++) {
                    float4 k4 = *(const float4*)&ks[j][e4 * 4];
                    d0 = fmaf(qr[e4 * 4 + 0], k4.x, d0);
                    d1 = fmaf(qr[e4 * 4 + 1], k4.y, d1);
                    d2 = fmaf(qr[e4 * 4 + 2], k4.z, d2);
                    d3 = fmaf(qr[e4 * 4 + 3], k4.w, d3);
                }
                float sc = (d0 + d1) + (d2 + d3);
                if (j >= jlo && j <= jhi) {
                    if (sc > m) {
                        float corr = __expf(m - sc);
                        m = sc;
                        l *= corr;
                        #pragma unroll
                        for (int e = 0; e < DH; e++) acc[e] *= corr;
                    }
                    float p = __expf(sc - m);
                    l += p;
                    #pragma unroll
                    for (int e4 = 0; e4 < 16; e4++) {
                        float4 v4 = *(const float4*)&vs[j][e4 * 4];
                        acc[e4 * 4 + 0] = fmaf(p, v4.x, acc[e4 * 4 + 0]);
                        acc[e4 * 4 + 1] = fmaf(p, v4.y, acc[e4 * 4 + 1]);
                        acc[e4 * 4 + 2] = fmaf(p, v4.z, acc[e4 * 4 + 2]);
                        acc[e4 * 4 + 3] = fmaf(p, v4.w, acc[e4 * 4 + 3]);
                    }
                }
            }
            __syncthreads();
        }
    }

    float inv_l = 1.0f / l;
    float* orow = g_attn + ((size_t)(b * SEQ + wi * WS + i) * INNER + h * DH);
    #pragma unroll
    for (int e4 = 0; e4 < 16; e4++) {
        float4 o4 = make_float4(acc[e4 * 4 + 0] * inv_l, acc[e4 * 4 + 1] * inv_l,
                                acc[e4 * 4 + 2] * inv_l, acc[e4 * 4 + 3] * inv_l);
        *(float4*)(orow + e4 * 4) = o4;
    }
}

// ---------------------------------------------------------------------------
// Launch: pure kernel launches, zero runtime API calls.
// ---------------------------------------------------------------------------
extern "C" void kernel_launch(void* const* d_in, const int* in_sizes, int n_in,
                              void* d_out, int out_size) {
    const float* x     = (const float*)d_in[0];
    const float* ln_g  = (const float*)d_in[1];
    const float* ln_b  = (const float*)d_in[2];
    const float* w_qkv = (const float*)d_in[3];
    const float* w_out = (const float*)d_in[4];
    float* out = (float*)d_out;

    rope_precompute_kernel<<<(JLEN * DH + 255) / 256, 256>>>();
    ln_kernel<<<M_ROWS, 256>>>(x, ln_g, ln_b);

    // qkv = xn @ w_qkv^T  (K=1024)
    gemm_mma<<<dim3(NT_N / 128, M_ROWS / 128), 256>>>(w_qkv, nullptr, DIM, 0);

    attn_kernel<<<dim3(NWIN, BATCH * HEADS), 128>>>();

    // out = attn @ w_out^T (K=512)
    gemm_mma<<<dim3(NT_N / 128, M_ROWS / 128), 256>>>(w_out, out, INNER, 1);
}

// round 8
// speedup vs baseline: 2.2838x; 1.2660x over previous
#include <cuda_runtime.h>
#include <cuda_bf16.h>
#include <math.h>
#include <stdint.h>

// ---------------------------------------------------------------------------
// Problem constants
// ---------------------------------------------------------------------------
#define BATCH 4
#define SEQ   4096
#define DIM   1024
#define HEADS 8
#define DH    64
#define WS    128
#define NWIN  32
#define INNER 512
#define JLEN  384
#define M_ROWS (BATCH * SEQ)   // 16384

#define NEG_INF (-3.402823466e+38f)

// ---------------------------------------------------------------------------
// Scratch (device globals; kernel_launch makes NO runtime API calls)
// ---------------------------------------------------------------------------
__device__ float g_xn  [M_ROWS * DIM];
__device__ float g_qkv [M_ROWS * DIM];
__device__ float g_attn[M_ROWS * INNER];
__device__ float g_kcos[JLEN * DH];
__device__ float g_ksin[JLEN * DH];
__device__ float g_qcs [WS * DH];
__device__ float g_qsn [WS * DH];

// ---------------------------------------------------------------------------
// Helpers
// ---------------------------------------------------------------------------
__device__ __forceinline__ float f2tf32(float x) {
    uint32_t y;
    asm("cvt.rna.tf32.f32 %0, %1;" : "=r"(y) : "f"(x));
    return __uint_as_float(y);
}

__device__ __forceinline__ void mma_tf32(float* d,
                                         float a0, float a1,
                                         float a2, float a3,
                                         float b0, float b1) {
    asm volatile(
        "mma.sync.aligned.m16n8k8.row.col.f32.tf32.tf32.f32 "
        "{%0,%1,%2,%3}, {%4,%5,%6,%7}, {%8,%9}, {%0,%1,%2,%3};\n"
        : "+f"(d[0]), "+f"(d[1]), "+f"(d[2]), "+f"(d[3])
        : "r"(__float_as_uint(a0)), "r"(__float_as_uint(a1)),
          "r"(__float_as_uint(a2)), "r"(__float_as_uint(a3)),
          "r"(__float_as_uint(b0)), "r"(__float_as_uint(b1)));
}

#define PERM(j) (((j) & 3) * 8 + ((j) >> 2))

// ---------------------------------------------------------------------------
// Rotary / xpos coefficient precompute
// ---------------------------------------------------------------------------
__global__ void rope_precompute_kernel() {
    int idx = blockIdx.x * blockDim.x + threadIdx.x;
    if (idx >= JLEN * DH) return;
    int t = idx / DH;
    int e = idx % DH;
    int f = e & 31;
    float invf = powf(10000.0f, -(2.0f * (float)f) / (float)DH);
    float ang  = (float)t * invf;
    float sb   = (2.0f * (float)f + 0.4f * (float)DH) / (1.4f * (float)DH);
    float pw   = ((float)t - (float)(JLEN / 2)) / (float)(WS / 2);
    float sc   = powf(sb, pw);
    float c = cosf(ang), s = sinf(ang);
    g_kcos[idx] = c / sc;
    g_ksin[idx] = s / sc;
    if (t >= JLEN - WS) {
        int i = t - (JLEN - WS);
        g_qcs[i * DH + e] = c * sc * 0.125f;
        g_qsn[i * DH + e] = s * sc * 0.125f;
    }
}

// ---------------------------------------------------------------------------
// LayerNorm
// ---------------------------------------------------------------------------
__global__ void __launch_bounds__(256) ln_kernel(const float* __restrict__ x,
                                                 const float* __restrict__ gam,
                                                 const float* __restrict__ bet) {
    __shared__ float red [8];
    __shared__ float red2[8];
    __shared__ float s_mu, s_rstd;
    int row = blockIdx.x;
    int t = threadIdx.x;
    float4 v = ((const float4*)(x + (size_t)row * DIM))[t];
    float s  = v.x + v.y + v.z + v.w;
    float sq = v.x * v.x + v.y * v.y + v.z * v.z + v.w * v.w;
    #pragma unroll
    for (int o = 16; o > 0; o >>= 1) {
        s  += __shfl_xor_sync(0xffffffffu, s,  o);
        sq += __shfl_xor_sync(0xffffffffu, sq, o);
    }
    if ((t & 31) == 0) { red[t >> 5] = s; red2[t >> 5] = sq; }
    __syncthreads();
    if (t < 32) {
        float ss = (t < 8) ? red [t] : 0.0f;
        float qq = (t < 8) ? red2[t] : 0.0f;
        #pragma unroll
        for (int o = 4; o > 0; o >>= 1) {
            ss += __shfl_xor_sync(0xffffffffu, ss, o);
            qq += __shfl_xor_sync(0xffffffffu, qq, o);
        }
        if (t == 0) {
            float mu  = ss * (1.0f / DIM);
            float var = qq * (1.0f / DIM) - mu * mu;
            s_mu = mu;
            s_rstd = rsqrtf(var + 1e-5f);
        }
    }
    __syncthreads();
    float mu = s_mu, rstd = s_rstd;
    float4 gg = ((const float4*)gam)[t];
    float4 bb = ((const float4*)bet)[t];
    float4 o4;
    o4.x = (v.x - mu) * rstd * gg.x + bb.x;
    o4.y = (v.y - mu) * rstd * gg.y + bb.y;
    o4.z = (v.z - mu) * rstd * gg.z + bb.z;
    o4.w = (v.w - mu) * rstd * gg.w + bb.w;
    ((float4*)(g_xn + (size_t)row * DIM))[t] = o4;
}

// ---------------------------------------------------------------------------
// TF32 mma.sync GEMM (NT) — unchanged from R6 passing version.
// ---------------------------------------------------------------------------
#define SA 36
#define NT_N 1024

__global__ void __launch_bounds__(256) gemm_mma(const float* __restrict__ Bmat,
                                                float* __restrict__ Cext,
                                                int K, int which) {
    __shared__ float As[128 * SA];
    __shared__ float Bs[128 * SA];

    const float* __restrict__ A = which ? g_attn : g_xn;
    float* __restrict__ C       = which ? Cext : g_qkv;

    const int tid  = threadIdx.x;
    const int bn   = blockIdx.x * 128;
    const int bm   = blockIdx.y * 128;
    const int warp = tid >> 5;
    const int lane = tid & 31;
    const int wm   = warp & 3;
    const int wn   = warp >> 2;
    const int r    = lane >> 2;
    const int c    = lane & 3;
    const int r0   = tid >> 3;
    const int u    = tid & 7;

    float acc[2][8][4];
    #pragma unroll
    for (int mt = 0; mt < 2; mt++)
        #pragma unroll
        for (int nt = 0; nt < 8; nt++)
            #pragma unroll
            for (int q = 0; q < 4; q++) acc[mt][nt][q] = 0.0f;

    const float* ag = A    + (size_t)(bm + r0) * K + u * 4;
    const float* bg = Bmat + (size_t)(bn + r0) * K + u * 4;

    float4 pa[4], pb[4];
    #pragma unroll
    for (int p = 0; p < 4; p++) {
        pa[p] = *(const float4*)(ag + (size_t)p * 32 * K);
        pb[p] = *(const float4*)(bg + (size_t)p * 32 * K);
    }

    for (int k0 = 0; k0 < K; k0 += 32) {
        #pragma unroll
        for (int p = 0; p < 4; p++) {
            int m = r0 + p * 32;
            As[m * SA +  0 + u] = f2tf32(pa[p].x);
            As[m * SA +  8 + u] = f2tf32(pa[p].y);
            As[m * SA + 16 + u] = f2tf32(pa[p].z);
            As[m * SA + 24 + u] = f2tf32(pa[p].w);
            Bs[m * SA +  0 + u] = f2tf32(pb[p].x);
            Bs[m * SA +  8 + u] = f2tf32(pb[p].y);
            Bs[m * SA + 16 + u] = f2tf32(pb[p].z);
            Bs[m * SA + 24 + u] = f2tf32(pb[p].w);
        }
        __syncthreads();

        if (k0 + 32 < K) {
            #pragma unroll
            for (int p = 0; p < 4; p++) {
                pa[p] = *(const float4*)(ag + (size_t)(k0 + 32) + (size_t)p * 32 * K);
                pb[p] = *(const float4*)(bg + (size_t)(k0 + 32) + (size_t)p * 32 * K);
            }
        }

        float aL[2][2][4], aH[2][2][4];
        #pragma unroll
        for (int mt = 0; mt < 2; mt++) {
            int rl = wm * 32 + mt * 16 + r;
            *(float4*)aL[mt][0] = *(const float4*)&As[rl * SA + c * 8];
            *(float4*)aL[mt][1] = *(const float4*)&As[rl * SA + c * 8 + 4];
            *(float4*)aH[mt][0] = *(const float4*)&As[(rl + 8) * SA + c * 8];
            *(float4*)aH[mt][1] = *(const float4*)&As[(rl + 8) * SA + c * 8 + 4];
        }

        #pragma unroll
        for (int nt = 0; nt < 8; nt++) {
            float bb[2][4];
            int nr = wn * 64 + nt * 8 + r;
            *(float4*)bb[0] = *(const float4*)&Bs[nr * SA + c * 8];
            *(float4*)bb[1] = *(const float4*)&Bs[nr * SA + c * 8 + 4];
            #pragma unroll
            for (int mt = 0; mt < 2; mt++) {
                #pragma unroll
                for (int s = 0; s < 4; s++) {
                    int q = s >> 1, o = (s & 1) * 2;
                    mma_tf32(acc[mt][nt],
                             aL[mt][q][o], aH[mt][q][o],
                             aL[mt][q][o + 1], aH[mt][q][o + 1],
                             bb[q][o], bb[q][o + 1]);
                }
            }
        }
        __syncthreads();
    }

    #pragma unroll
    for (int mt = 0; mt < 2; mt++) {
        #pragma unroll
        for (int nt = 0; nt < 8; nt++) {
            int row = bm + wm * 32 + mt * 16 + r;
            int col = bn + wn * 64 + nt * 8 + 2 * c;
            *(float2*)&C[(size_t)row * NT_N + col] =
                make_float2(acc[mt][nt][0], acc[mt][nt][1]);
            *(float2*)&C[(size_t)(row + 8) * NT_N + col] =
                make_float2(acc[mt][nt][2], acc[mt][nt][3]);
        }
    }
}

// ---------------------------------------------------------------------------
// Tensor-core flash attention.
// Grid (NWIN, BATCH*HEADS), 256 threads = 8 warps; warp w owns q rows
// [16w, 16w+16). Context (384 rows = windows wi-1..wi+1) streamed in 32-row
// chunks. Per chunk: S = Q.K^T via mma -> smem (permuted cols); 128 scalar
// threads do online softmax (fp32 exp) writing P back permuted; O += P.V via
// mma with corr rescale. All mma inputs rna-rounded to tf32.
// ---------------------------------------------------------------------------
struct AttnSmem {
    union {
        struct {
            float ks0[32][36];   // k rot, e 0..31 permuted
            float ks1[32][36];   // k rot, e 32..63 permuted
            float vsT[64][36];   // v^T: [e][perm(j)]
        } kv;
        float qstage[64][68];    // phase-0 staging only
    } u;
    float Ss[128 * 36];          // raw k/v staging OR S/P (permuted cols)
    float corr[128];
    float lrow[128];
};

__global__ void __launch_bounds__(256) attn_kernel() {
    __shared__ AttnSmem sm;

    const int wi   = blockIdx.x;
    const int bh   = blockIdx.y;
    const int b    = bh >> 3;
    const int h    = bh & 7;
    const int tid  = threadIdx.x;
    const int warp = tid >> 5;
    const int lane = tid & 31;
    const int r    = lane >> 2;
    const int c    = lane & 3;
    const int row0 = warp * 16;          // warp's q-row base

    const float* __restrict__ qkv = g_qkv;

    // ---------------- phase 0: q fragments (rotated, tf32) ----------------
    float qa[8][4];
    #pragma unroll
    for (int half = 0; half < 2; half++) {
        {   // coalesced stage of raw q rows [64*half, 64*half+64)
            int sr = tid >> 2, quad = tid & 3;
            const float* qg = qkv +
                (size_t)(b * SEQ + wi * WS + half * 64 + sr) * DIM + h * DH;
            #pragma unroll
            for (int p = 0; p < 4; p++)
                *(float4*)&sm.u.qstage[sr][p * 16 + quad * 4] =
                    *(const float4*)(qg + p * 16 + quad * 4);
        }
        __syncthreads();
        #pragma unroll
        for (int p = 0; p < 8; p++) {       // rotate in place (2048 pairs)
            int idx = p * 256 + tid;
            int sr = idx >> 5, e = idx & 31;
            int gi = (half * 64 + sr) * DH;
            float x1 = sm.u.qstage[sr][e], x2 = sm.u.qstage[sr][e + 32];
            float c1 = g_qcs[gi + e],      s1 = g_qsn[gi + e];
            float c2 = g_qcs[gi + e + 32], s2 = g_qsn[gi + e + 32];
            sm.u.qstage[sr][e]      = f2tf32(x1 * c1 - x2 * s1);
            sm.u.qstage[sr][e + 32] = f2tf32(x2 * c2 + x1 * s2);
        }
        __syncthreads();
        if ((warp >> 2) == half) {
            int lr = (warp & 3) * 16 + r;
            #pragma unroll
            for (int kk = 0; kk < 8; kk++) {
                qa[kk][0] = sm.u.qstage[lr][kk * 8 + c];
                qa[kk][1] = sm.u.qstage[lr + 8][kk * 8 + c];
                qa[kk][2] = sm.u.qstage[lr][kk * 8 + c + 4];
                qa[kk][3] = sm.u.qstage[lr + 8][kk * 8 + c + 4];
            }
        }
        __syncthreads();
    }

    float Oacc[8][4];
    #pragma unroll
    for (int nt = 0; nt < 8; nt++)
        #pragma unroll
        for (int q = 0; q < 4; q++) Oacc[nt][q] = 0.0f;

    float m_run = NEG_INF, l_run = 0.0f;     // used by tid < 128

    // ---------------- chunk loop ----------------
    for (int ch = 0; ch < 12; ch++) {
        int kw = wi - 1 + (ch >> 2);
        if (kw < 0 || kw >= NWIN) continue;

        // (a) raw k chunk -> Ss region (coalesced)
        {
            int j = tid >> 3, u8 = tid & 7;
            const float* kg = qkv +
                (size_t)(b * SEQ + (wi - 1) * WS + ch * 32 + j) * DIM + h * DH;
            *(float4*)&sm.Ss[j * 64 + u8 * 8]     = *(const float4*)(kg + u8 * 8);
            *(float4*)&sm.Ss[j * 64 + u8 * 8 + 4] = *(const float4*)(kg + u8 * 8 + 4);
        }
        __syncthreads();
        // (b) rotate + permute k -> ks0/ks1
        #pragma unroll
        for (int p = 0; p < 4; p++) {
            int idx = p * 256 + tid;         // 1024 pairs
            int j = idx >> 5, e = idx & 31;
            int gi = (ch * 32 + j) * DH;
            float x1 = sm.Ss[j * 64 + e], x2 = sm.Ss[j * 64 + e + 32];
            float c1 = g_kcos[gi + e],      s1 = g_ksin[gi + e];
            float c2 = g_kcos[gi + e + 32], s2 = g_ksin[gi + e + 32];
            sm.u.kv.ks0[j][PERM(e)] = f2tf32(x1 * c1 - x2 * s1);
            sm.u.kv.ks1[j][PERM(e)] = f2tf32(x2 * c2 + x1 * s2);
        }
        __syncthreads();
        // (c) raw v chunk -> Ss region
        {
            int j = tid >> 3, u8 = tid & 7;
            const float* vg = qkv +
                (size_t)(b * SEQ + (wi - 1) * WS + ch * 32 + j) * DIM
                + INNER + h * DH;
            *(float4*)&sm.Ss[j * 64 + u8 * 8]     = *(const float4*)(vg + u8 * 8);
            *(float4*)&sm.Ss[j * 64 + u8 * 8 + 4] = *(const float4*)(vg + u8 * 8 + 4);
        }
        __syncthreads();
        // (d) transpose+permute v -> vsT[e][perm(j)]
        #pragma unroll
        for (int p = 0; p < 8; p++) {
            int idx = p * 256 + tid;         // 2048 elems
            int j = idx >> 6, e = idx & 63;
            sm.u.kv.vsT[e][PERM(j)] = f2tf32(sm.Ss[j * 64 + e]);
        }
        __syncthreads();

        // ---- S = Q.K^T (M=128 per block, N=32, K=64) ----
        float Sacc[4][4];
        #pragma unroll
        for (int nt = 0; nt < 4; nt++)
            #pragma unroll
            for (int q = 0; q < 4; q++) Sacc[nt][q] = 0.0f;
        #pragma unroll
        for (int nt = 0; nt < 4; nt++) {
            float bbA[2][4], bbB[2][4];
            int nr = nt * 8 + r;
            *(float4*)bbA[0] = *(const float4*)&sm.u.kv.ks0[nr][c * 8];
            *(float4*)bbA[1] = *(const float4*)&sm.u.kv.ks0[nr][c * 8 + 4];
            *(float4*)bbB[0] = *(const float4*)&sm.u.kv.ks1[nr][c * 8];
            *(float4*)bbB[1] = *(const float4*)&sm.u.kv.ks1[nr][c * 8 + 4];
            #pragma unroll
            for (int s = 0; s < 4; s++) {
                int q = s >> 1, o = (s & 1) * 2;
                mma_tf32(Sacc[nt], qa[s][0], qa[s][1], qa[s][2], qa[s][3],
                         bbA[q][o], bbA[q][o + 1]);
            }
            #pragma unroll
            for (int s = 0; s < 4; s++) {
                int q = s >> 1, o = (s & 1) * 2;
                mma_tf32(Sacc[nt], qa[4 + s][0], qa[4 + s][1],
                         qa[4 + s][2], qa[4 + s][3],
                         bbB[q][o], bbB[q][o + 1]);
            }
        }
        // store S -> Ss (permuted cols); Ss raw-v already consumed (sync above)
        #pragma unroll
        for (int nt = 0; nt < 4; nt++) {
            int j0 = nt * 8 + 2 * c;
            sm.Ss[(row0 + r) * 36 + PERM(j0)]         = Sacc[nt][0];
            sm.Ss[(row0 + r) * 36 + PERM(j0 + 1)]     = Sacc[nt][1];
            sm.Ss[(row0 + r + 8) * 36 + PERM(j0)]     = Sacc[nt][2];
            sm.Ss[(row0 + r + 8) * 36 + PERM(j0 + 1)] = Sacc[nt][3];
        }
        __syncthreads();

        // ---- scalar online softmax (128 threads, one per row) ----
        if (tid < 128) {
            int row = tid;
            int jlo = row - ch * 32;      if (jlo < 0)  jlo = 0;
            int jhi = row + 256 - ch * 32; if (jhi > 31) jhi = 31;
            float cr = 1.0f;
            if (jlo <= jhi) {
                float mc = NEG_INF;
                for (int j = jlo; j <= jhi; j++)
                    mc = fmaxf(mc, sm.Ss[row * 36 + PERM(j)]);
                float mnew = fmaxf(m_run, mc);
                cr = __expf(m_run - mnew);       // m_run=-inf -> 0
                float sum = 0.0f;
                #pragma unroll 4
                for (int j = 0; j < 32; j++) {
                    float p = 0.0f;
                    if (j >= jlo && j <= jhi) {
                        p = __expf(sm.Ss[row * 36 + PERM(j)] - mnew);
                        sum += p;
                    }
                    sm.Ss[row * 36 + PERM(j)] = f2tf32(p);
                }
                l_run = l_run * cr + sum;
                m_run = mnew;
            } else {
                #pragma unroll 4
                for (int j = 0; j < 32; j++)
                    sm.Ss[row * 36 + PERM(j)] = 0.0f;
            }
            sm.corr[row] = cr;
        }
        __syncthreads();

        // ---- O = O*corr + P.V  (K=32, N=64) ----
        float cr0 = sm.corr[row0 + r], cr1 = sm.corr[row0 + r + 8];
        #pragma unroll
        for (int nt = 0; nt < 8; nt++) {
            Oacc[nt][0] *= cr0; Oacc[nt][1] *= cr0;
            Oacc[nt][2] *= cr1; Oacc[nt][3] *= cr1;
        }
        float paL[2][4], paH[2][4];
        *(float4*)paL[0] = *(const float4*)&sm.Ss[(row0 + r) * 36 + c * 8];
        *(float4*)paL[1] = *(const float4*)&sm.Ss[(row0 + r) * 36 + c * 8 + 4];
        *(float4*)paH[0] = *(const float4*)&sm.Ss[(row0 + r + 8) * 36 + c * 8];
        *(float4*)paH[1] = *(const float4*)&sm.Ss[(row0 + r + 8) * 36 + c * 8 + 4];
        #pragma unroll
        for (int nt = 0; nt < 8; nt++) {
            float bb[2][4];
            int nr = nt * 8 + r;
            *(float4*)bb[0] = *(const float4*)&sm.u.kv.vsT[nr][c * 8];
            *(float4*)bb[1] = *(const float4*)&sm.u.kv.vsT[nr][c * 8 + 4];
            #pragma unroll
            for (int s = 0; s < 4; s++) {
                int q = s >> 1, o = (s & 1) * 2;
                mma_tf32(Oacc[nt], paL[q][o], paH[q][o],
                         paL[q][o + 1], paH[q][o + 1],
                         bb[q][o], bb[q][o + 1]);
            }
        }
        __syncthreads();    // before next chunk overwrites Ss/kv
    }

    // ---------------- finalize ----------------
    if (tid < 128) sm.lrow[tid] = l_run;
    __syncthreads();
    float inv0 = 1.0f / sm.lrow[row0 + r];
    float inv1 = 1.0f / sm.lrow[row0 + r + 8];
    float* ob = g_attn + (size_t)(b * SEQ + wi * WS) * INNER + h * DH;
    #pragma unroll
    for (int nt = 0; nt < 8; nt++) {
        int col = nt * 8 + 2 * c;
        *(float2*)&ob[(size_t)(row0 + r) * INNER + col] =
            make_float2(Oacc[nt][0] * inv0, Oacc[nt][1] * inv0);
        *(float2*)&ob[(size_t)(row0 + r + 8) * INNER + col] =
            make_float2(Oacc[nt][2] * inv1, Oacc[nt][3] * inv1);
    }
}

// ---------------------------------------------------------------------------
// Launch: pure kernel launches, zero runtime API calls.
// ---------------------------------------------------------------------------
extern "C" void kernel_launch(void* const* d_in, const int* in_sizes, int n_in,
                              void* d_out, int out_size) {
    const float* x     = (const float*)d_in[0];
    const float* ln_g  = (const float*)d_in[1];
    const float* ln_b  = (const float*)d_in[2];
    const float* w_qkv = (const float*)d_in[3];
    const float* w_out = (const float*)d_in[4];
    float* out = (float*)d_out;

    rope_precompute_kernel<<<(JLEN * DH + 255) / 256, 256>>>();
    ln_kernel<<<M_ROWS, 256>>>(x, ln_g, ln_b);

    // qkv = xn @ w_qkv^T  (K=1024)
    gemm_mma<<<dim3(NT_N / 128, M_ROWS / 128), 256>>>(w_qkv, nullptr, DIM, 0);

    attn_kernel<<<dim3(NWIN, BATCH * HEADS), 256>>>();

    // out = attn @ w_out^T (K=512)
    gemm_mma<<<dim3(NT_N / 128, M_ROWS / 128), 256>>>(w_out, out, INNER, 1);
}

// round 9
// speedup vs baseline: 2.3846x; 1.0441x over previous
#include <cuda_runtime.h>
#include <cuda_bf16.h>
#include <math.h>
#include <stdint.h>

// ---------------------------------------------------------------------------
// Problem constants
// ---------------------------------------------------------------------------
#define BATCH 4
#define SEQ   4096
#define DIM   1024
#define HEADS 8
#define DH    64
#define WS    128
#define NWIN  32
#define INNER 512
#define JLEN  384
#define M_ROWS (BATCH * SEQ)   // 16384

#define NEG_INF (-3.402823466e+38f)

// ---------------------------------------------------------------------------
// Scratch (device globals; kernel_launch makes NO runtime API calls)
// ---------------------------------------------------------------------------
__device__ float g_xn  [M_ROWS * DIM];
__device__ float g_qkv [M_ROWS * DIM];
__device__ float g_attn[M_ROWS * INNER];
__device__ float g_kcos[JLEN * DH];
__device__ float g_ksin[JLEN * DH];
__device__ float g_qcs [WS * DH];
__device__ float g_qsn [WS * DH];

// ---------------------------------------------------------------------------
// Helpers
// ---------------------------------------------------------------------------
__device__ __forceinline__ float f2tf32(float x) {
    uint32_t y;
    asm("cvt.rna.tf32.f32 %0, %1;" : "=r"(y) : "f"(x));
    return __uint_as_float(y);
}

__device__ __forceinline__ void mma_tf32(float* d,
                                         float a0, float a1,
                                         float a2, float a3,
                                         float b0, float b1) {
    asm volatile(
        "mma.sync.aligned.m16n8k8.row.col.f32.tf32.tf32.f32 "
        "{%0,%1,%2,%3}, {%4,%5,%6,%7}, {%8,%9}, {%0,%1,%2,%3};\n"
        : "+f"(d[0]), "+f"(d[1]), "+f"(d[2]), "+f"(d[3])
        : "r"(__float_as_uint(a0)), "r"(__float_as_uint(a1)),
          "r"(__float_as_uint(a2)), "r"(__float_as_uint(a3)),
          "r"(__float_as_uint(b0)), "r"(__float_as_uint(b1)));
}

__device__ __forceinline__ uint32_t cvta_smem(const void* p) {
    uint32_t a;
    asm("{ .reg .u64 t; cvta.to.shared.u64 t, %1; cvt.u32.u64 %0, t; }"
        : "=r"(a) : "l"(p));
    return a;
}

#define PERM(j) (((j) & 3) * 8 + ((j) >> 2))

// ---------------------------------------------------------------------------
// Rotary / xpos coefficient precompute
// ---------------------------------------------------------------------------
__global__ void rope_precompute_kernel() {
    int idx = blockIdx.x * blockDim.x + threadIdx.x;
    if (idx >= JLEN * DH) return;
    int t = idx / DH;
    int e = idx % DH;
    int f = e & 31;
    float invf = powf(10000.0f, -(2.0f * (float)f) / (float)DH);
    float ang  = (float)t * invf;
    float sb   = (2.0f * (float)f + 0.4f * (float)DH) / (1.4f * (float)DH);
    float pw   = ((float)t - (float)(JLEN / 2)) / (float)(WS / 2);
    float sc   = powf(sb, pw);
    float c = cosf(ang), s = sinf(ang);
    g_kcos[idx] = c / sc;
    g_ksin[idx] = s / sc;
    if (t >= JLEN - WS) {
        int i = t - (JLEN - WS);
        g_qcs[i * DH + e] = c * sc * 0.125f;
        g_qsn[i * DH + e] = s * sc * 0.125f;
    }
}

// ---------------------------------------------------------------------------
// LayerNorm
// ---------------------------------------------------------------------------
__global__ void __launch_bounds__(256) ln_kernel(const float* __restrict__ x,
                                                 const float* __restrict__ gam,
                                                 const float* __restrict__ bet) {
    __shared__ float red [8];
    __shared__ float red2[8];
    __shared__ float s_mu, s_rstd;
    int row = blockIdx.x;
    int t = threadIdx.x;
    float4 v = ((const float4*)(x + (size_t)row * DIM))[t];
    float s  = v.x + v.y + v.z + v.w;
    float sq = v.x * v.x + v.y * v.y + v.z * v.z + v.w * v.w;
    #pragma unroll
    for (int o = 16; o > 0; o >>= 1) {
        s  += __shfl_xor_sync(0xffffffffu, s,  o);
        sq += __shfl_xor_sync(0xffffffffu, sq, o);
    }
    if ((t & 31) == 0) { red[t >> 5] = s; red2[t >> 5] = sq; }
    __syncthreads();
    if (t < 32) {
        float ss = (t < 8) ? red [t] : 0.0f;
        float qq = (t < 8) ? red2[t] : 0.0f;
        #pragma unroll
        for (int o = 4; o > 0; o >>= 1) {
            ss += __shfl_xor_sync(0xffffffffu, ss, o);
            qq += __shfl_xor_sync(0xffffffffu, qq, o);
        }
        if (t == 0) {
            float mu  = ss * (1.0f / DIM);
            float var = qq * (1.0f / DIM) - mu * mu;
            s_mu = mu;
            s_rstd = rsqrtf(var + 1e-5f);
        }
    }
    __syncthreads();
    float mu = s_mu, rstd = s_rstd;
    float4 gg = ((const float4*)gam)[t];
    float4 bb = ((const float4*)bet)[t];
    float4 o4;
    o4.x = (v.x - mu) * rstd * gg.x + bb.x;
    o4.y = (v.y - mu) * rstd * gg.y + bb.y;
    o4.z = (v.z - mu) * rstd * gg.z + bb.z;
    o4.w = (v.w - mu) * rstd * gg.w + bb.w;
    ((float4*)(g_xn + (size_t)row * DIM))[t] = o4;
}

// ---------------------------------------------------------------------------
// TF32 mma.sync GEMM (NT): no register prefetch; per-iter LDG->cvt->STS.
// __launch_bounds__(256,2) targets 2 CTAs/SM so cross-CTA overlap hides the
// load phase that a single resident CTA serialized in R8.
// ---------------------------------------------------------------------------
#define SA 36
#define NT_N 1024

__global__ void __launch_bounds__(256, 2) gemm_mma(const float* __restrict__ Bmat,
                                                   float* __restrict__ Cext,
                                                   int K, int which) {
    __shared__ float As[128 * SA];
    __shared__ float Bs[128 * SA];

    const float* __restrict__ A = which ? g_attn : g_xn;
    float* __restrict__ C       = which ? Cext : g_qkv;

    const int tid  = threadIdx.x;
    const int bn   = blockIdx.x * 128;
    const int bm   = blockIdx.y * 128;
    const int warp = tid >> 5;
    const int lane = tid & 31;
    const int wm   = warp & 3;
    const int wn   = warp >> 2;
    const int r    = lane >> 2;
    const int c    = lane & 3;
    const int r0   = tid >> 3;
    const int u    = tid & 7;

    float acc[2][8][4];
    #pragma unroll
    for (int mt = 0; mt < 2; mt++)
        #pragma unroll
        for (int nt = 0; nt < 8; nt++)
            #pragma unroll
            for (int q = 0; q < 4; q++) acc[mt][nt][q] = 0.0f;

    const float* ag = A    + (size_t)(bm + r0) * K + u * 4;
    const float* bg = Bmat + (size_t)(bn + r0) * K + u * 4;

    for (int k0 = 0; k0 < K; k0 += 32) {
        #pragma unroll
        for (int p = 0; p < 4; p++) {
            int m = r0 + p * 32;
            float4 av = *(const float4*)(ag + (size_t)k0 + (size_t)p * 32 * K);
            float4 bv = *(const float4*)(bg + (size_t)k0 + (size_t)p * 32 * K);
            As[m * SA +  0 + u] = f2tf32(av.x);
            As[m * SA +  8 + u] = f2tf32(av.y);
            As[m * SA + 16 + u] = f2tf32(av.z);
            As[m * SA + 24 + u] = f2tf32(av.w);
            Bs[m * SA +  0 + u] = f2tf32(bv.x);
            Bs[m * SA +  8 + u] = f2tf32(bv.y);
            Bs[m * SA + 16 + u] = f2tf32(bv.z);
            Bs[m * SA + 24 + u] = f2tf32(bv.w);
        }
        __syncthreads();

        float aL[2][2][4], aH[2][2][4];
        #pragma unroll
        for (int mt = 0; mt < 2; mt++) {
            int rl = wm * 32 + mt * 16 + r;
            *(float4*)aL[mt][0] = *(const float4*)&As[rl * SA + c * 8];
            *(float4*)aL[mt][1] = *(const float4*)&As[rl * SA + c * 8 + 4];
            *(float4*)aH[mt][0] = *(const float4*)&As[(rl + 8) * SA + c * 8];
            *(float4*)aH[mt][1] = *(const float4*)&As[(rl + 8) * SA + c * 8 + 4];
        }

        #pragma unroll
        for (int nt = 0; nt < 8; nt++) {
            float bb[2][4];
            int nr = wn * 64 + nt * 8 + r;
            *(float4*)bb[0] = *(const float4*)&Bs[nr * SA + c * 8];
            *(float4*)bb[1] = *(const float4*)&Bs[nr * SA + c * 8 + 4];
            #pragma unroll
            for (int mt = 0; mt < 2; mt++) {
                #pragma unroll
                for (int s = 0; s < 4; s++) {
                    int q = s >> 1, o = (s & 1) * 2;
                    mma_tf32(acc[mt][nt],
                             aL[mt][q][o], aH[mt][q][o],
                             aL[mt][q][o + 1], aH[mt][q][o + 1],
                             bb[q][o], bb[q][o + 1]);
                }
            }
        }
        __syncthreads();
    }

    #pragma unroll
    for (int mt = 0; mt < 2; mt++) {
        #pragma unroll
        for (int nt = 0; nt < 8; nt++) {
            int row = bm + wm * 32 + mt * 16 + r;
            int col = bn + wn * 64 + nt * 8 + 2 * c;
            *(float2*)&C[(size_t)row * NT_N + col] =
                make_float2(acc[mt][nt][0], acc[mt][nt][1]);
            *(float2*)&C[(size_t)(row + 8) * NT_N + col] =
                make_float2(acc[mt][nt][2], acc[mt][nt][3]);
        }
    }
}

// ---------------------------------------------------------------------------
// Tensor-core flash attention v2.
// k: direct global load + fused rotation (no staging). v: cp.async prefetch
// into vstage, transposed by threads 128-255 concurrently with the 128-thread
// softmax. 3 syncthreads per chunk (was 7).
// ---------------------------------------------------------------------------
struct AttnSmem {
    union {
        struct {
            float ks0[32][36];   // k rot, e 0..31 permuted
            float ks1[32][36];   // k rot, e 32..63 permuted
            float vsT[64][36];   // v^T: [e][perm(j)]
        } kv;
        float qstage[64][68];    // phase-0 staging only
    } u;                          // 18432 B
    float Ss[128 * 36];           // 18432 B   S / P (permuted cols)
    float vstage[32][64];         // 8192 B    raw v chunk (cp.async dst)
    float corr[128];
    float lrow[128];
};                                // ~46.1 KB static

__global__ void __launch_bounds__(256) attn_kernel() {
    __shared__ AttnSmem sm;

    const int wi   = blockIdx.x;
    const int bh   = blockIdx.y;
    const int b    = bh >> 3;
    const int h    = bh & 7;
    const int tid  = threadIdx.x;
    const int warp = tid >> 5;
    const int lane = tid & 31;
    const int r    = lane >> 2;
    const int c    = lane & 3;
    const int row0 = warp * 16;          // warp's q-row base

    const float* __restrict__ qkv = g_qkv;

    // ---------------- phase 0: q fragments (rotated, tf32) ----------------
    float qa[8][4];
    #pragma unroll
    for (int half = 0; half < 2; half++) {
        {   // coalesced stage of raw q rows [64*half, 64*half+64)
            int sr = tid >> 2, quad = tid & 3;
            const float* qg = qkv +
                (size_t)(b * SEQ + wi * WS + half * 64 + sr) * DIM + h * DH;
            #pragma unroll
            for (int p = 0; p < 4; p++)
                *(float4*)&sm.u.qstage[sr][p * 16 + quad * 4] =
                    *(const float4*)(qg + p * 16 + quad * 4);
        }
        __syncthreads();
        #pragma unroll
        for (int p = 0; p < 8; p++) {       // rotate in place (2048 pairs)
            int idx = p * 256 + tid;
            int sr = idx >> 5, e = idx & 31;
            int gi = (half * 64 + sr) * DH;
            float x1 = sm.u.qstage[sr][e], x2 = sm.u.qstage[sr][e + 32];
            float c1 = g_qcs[gi + e],      s1 = g_qsn[gi + e];
            float c2 = g_qcs[gi + e + 32], s2 = g_qsn[gi + e + 32];
            sm.u.qstage[sr][e]      = f2tf32(x1 * c1 - x2 * s1);
            sm.u.qstage[sr][e + 32] = f2tf32(x2 * c2 + x1 * s2);
        }
        __syncthreads();
        if ((warp >> 2) == half) {
            int lr = (warp & 3) * 16 + r;
            #pragma unroll
            for (int kk = 0; kk < 8; kk++) {
                qa[kk][0] = sm.u.qstage[lr][kk * 8 + c];
                qa[kk][1] = sm.u.qstage[lr + 8][kk * 8 + c];
                qa[kk][2] = sm.u.qstage[lr][kk * 8 + c + 4];
                qa[kk][3] = sm.u.qstage[lr + 8][kk * 8 + c + 4];
            }
        }
        __syncthreads();
    }

    float Oacc[8][4];
    #pragma unroll
    for (int nt = 0; nt < 8; nt++)
        #pragma unroll
        for (int q = 0; q < 4; q++) Oacc[nt][q] = 0.0f;

    float m_run = NEG_INF, l_run = 0.0f;     // used by tid < 128

    const uint32_t vstage_base = cvta_smem(&sm.vstage[0][0]);

    // ---------------- chunk loop (3 syncs per chunk) ----------------
    for (int ch = 0; ch < 12; ch++) {
        int kw = wi - 1 + (ch >> 2);
        if (kw < 0 || kw >= NWIN) continue;

        // (1) prefetch raw v chunk via cp.async (overlaps k-load + S-mma)
        {
            int j = tid >> 3, u8 = tid & 7;
            const float* vg = qkv +
                (size_t)(b * SEQ + (wi - 1) * WS + ch * 32 + j) * DIM
                + INNER + h * DH + u8 * 8;
            uint32_t dst = vstage_base + (uint32_t)(j * 64 + u8 * 8) * 4u;
            asm volatile("cp.async.cg.shared.global [%0], [%1], 16;"
                         :: "r"(dst), "l"(vg) : "memory");
            asm volatile("cp.async.cg.shared.global [%0], [%1], 16;"
                         :: "r"(dst + 16u), "l"(vg + 4) : "memory");
            asm volatile("cp.async.commit_group;" ::: "memory");
        }

        // (2) k: direct load + fused rotation + permuted store
        #pragma unroll
        for (int p = 0; p < 4; p++) {
            int j = (tid >> 5) + p * 8;
            int e = tid & 31;
            const float* kg = qkv +
                (size_t)(b * SEQ + (wi - 1) * WS + ch * 32 + j) * DIM + h * DH;
            float x1 = kg[e], x2 = kg[e + 32];
            int gi = (ch * 32 + j) * DH;
            sm.u.kv.ks0[j][PERM(e)] =
                f2tf32(x1 * g_kcos[gi + e] - x2 * g_ksin[gi + e]);
            sm.u.kv.ks1[j][PERM(e)] =
                f2tf32(x2 * g_kcos[gi + e + 32] + x1 * g_ksin[gi + e + 32]);
        }
        __syncthreads();   // S1: ks ready; also orders prev-chunk PV Ss reads
                           // before this chunk's S-store below

        // (3) S = Q.K^T (M=128, N=32, K=64)
        float Sacc[4][4];
        #pragma unroll
        for (int nt = 0; nt < 4; nt++)
            #pragma unroll
            for (int q = 0; q < 4; q++) Sacc[nt][q] = 0.0f;
        #pragma unroll
        for (int nt = 0; nt < 4; nt++) {
            float bbA[2][4], bbB[2][4];
            int nr = nt * 8 + r;
            *(float4*)bbA[0] = *(const float4*)&sm.u.kv.ks0[nr][c * 8];
            *(float4*)bbA[1] = *(const float4*)&sm.u.kv.ks0[nr][c * 8 + 4];
            *(float4*)bbB[0] = *(const float4*)&sm.u.kv.ks1[nr][c * 8];
            *(float4*)bbB[1] = *(const float4*)&sm.u.kv.ks1[nr][c * 8 + 4];
            #pragma unroll
            for (int s = 0; s < 4; s++) {
                int q = s >> 1, o = (s & 1) * 2;
                mma_tf32(Sacc[nt], qa[s][0], qa[s][1], qa[s][2], qa[s][3],
                         bbA[q][o], bbA[q][o + 1]);
            }
            #pragma unroll
            for (int s = 0; s < 4; s++) {
                int q = s >> 1, o = (s & 1) * 2;
                mma_tf32(Sacc[nt], qa[4 + s][0], qa[4 + s][1],
                         qa[4 + s][2], qa[4 + s][3],
                         bbB[q][o], bbB[q][o + 1]);
            }
        }
        #pragma unroll
        for (int nt = 0; nt < 4; nt++) {
            int j0 = nt * 8 + 2 * c;
            sm.Ss[(row0 + r) * 36 + PERM(j0)]         = Sacc[nt][0];
            sm.Ss[(row0 + r) * 36 + PERM(j0 + 1)]     = Sacc[nt][1];
            sm.Ss[(row0 + r + 8) * 36 + PERM(j0)]     = Sacc[nt][2];
            sm.Ss[(row0 + r + 8) * 36 + PERM(j0 + 1)] = Sacc[nt][3];
        }
        asm volatile("cp.async.wait_group 0;" ::: "memory");
        __syncthreads();   // S2: S visible; vstage complete

        // (4a) softmax on threads 0-127 (one row each)
        if (tid < 128) {
            int row = tid;
            int jlo = row - ch * 32;       if (jlo < 0)  jlo = 0;
            int jhi = row + 256 - ch * 32; if (jhi > 31) jhi = 31;
            float cr = 1.0f;
            if (jlo <= jhi) {
                float mc = NEG_INF;
                for (int j = jlo; j <= jhi; j++)
                    mc = fmaxf(mc, sm.Ss[row * 36 + PERM(j)]);
                float mnew = fmaxf(m_run, mc);
                cr = __expf(m_run - mnew);       // m_run=-inf -> 0
                float sum = 0.0f;
                #pragma unroll 4
                for (int j = 0; j < 32; j++) {
                    float p = 0.0f;
                    if (j >= jlo && j <= jhi) {
                        p = __expf(sm.Ss[row * 36 + PERM(j)] - mnew);
                        sum += p;
                    }
                    sm.Ss[row * 36 + PERM(j)] = f2tf32(p);
                }
                l_run = l_run * cr + sum;
                m_run = mnew;
            } else {
                #pragma unroll 4
                for (int j = 0; j < 32; j++)
                    sm.Ss[row * 36 + PERM(j)] = 0.0f;
            }
            sm.corr[row] = cr;
        } else {
            // (4b) concurrent v transpose+permute on threads 128-255
            int t2 = tid - 128;
            #pragma unroll
            for (int p = 0; p < 16; p++) {
                int idx = p * 128 + t2;
                int j = idx >> 6, e = idx & 63;
                sm.u.kv.vsT[e][PERM(j)] = f2tf32(sm.vstage[j][e]);
            }
        }
        __syncthreads();   // S3

        // (5) O = O*corr + P.V  (K=32, N=64)
        float cr0 = sm.corr[row0 + r], cr1 = sm.corr[row0 + r + 8];
        #pragma unroll
        for (int nt = 0; nt < 8; nt++) {
            Oacc[nt][0] *= cr0; Oacc[nt][1] *= cr0;
            Oacc[nt][2] *= cr1; Oacc[nt][3] *= cr1;
        }
        float paL[2][4], paH[2][4];
        *(float4*)paL[0] = *(const float4*)&sm.Ss[(row0 + r) * 36 + c * 8];
        *(float4*)paL[1] = *(const float4*)&sm.Ss[(row0 + r) * 36 + c * 8 + 4];
        *(float4*)paH[0] = *(const float4*)&sm.Ss[(row0 + r + 8) * 36 + c * 8];
        *(float4*)paH[1] = *(const float4*)&sm.Ss[(row0 + r + 8) * 36 + c * 8 + 4];
        #pragma unroll
        for (int nt = 0; nt < 8; nt++) {
            float bb[2][4];
            int nr = nt * 8 + r;
            *(float4*)bb[0] = *(const float4*)&sm.u.kv.vsT[nr][c * 8];
            *(float4*)bb[1] = *(const float4*)&sm.u.kv.vsT[nr][c * 8 + 4];
            #pragma unroll
            for (int s = 0; s < 4; s++) {
                int q = s >> 1, o = (s & 1) * 2;
                mma_tf32(Oacc[nt], paL[q][o], paH[q][o],
                         paL[q][o + 1], paH[q][o + 1],
                         bb[q][o], bb[q][o + 1]);
            }
        }
        // no end-of-chunk sync needed: next chunk writes ks/vstage (not read
        // by PV), and its S-store is fenced by S1.
    }

    // ---------------- finalize ----------------
    __syncthreads();
    if (tid < 128) sm.lrow[tid] = l_run;
    __syncthreads();
    float inv0 = 1.0f / sm.lrow[row0 + r];
    float inv1 = 1.0f / sm.lrow[row0 + r + 8];
    float* ob = g_attn + (size_t)(b * SEQ + wi * WS) * INNER + h * DH;
    #pragma unroll
    for (int nt = 0; nt < 8; nt++) {
        int col = nt * 8 + 2 * c;
        *(float2*)&ob[(size_t)(row0 + r) * INNER + col] =
            make_float2(Oacc[nt][0] * inv0, Oacc[nt][1] * inv0);
        *(float2*)&ob[(size_t)(row0 + r + 8) * INNER + col] =
            make_float2(Oacc[nt][2] * inv1, Oacc[nt][3] * inv1);
    }
}

// ---------------------------------------------------------------------------
// Launch: pure kernel launches, zero runtime API calls.
// ---------------------------------------------------------------------------
extern "C" void kernel_launch(void* const* d_in, const int* in_sizes, int n_in,
                              void* d_out, int out_size) {
    const float* x     = (const float*)d_in[0];
    const float* ln_g  = (const float*)d_in[1];
    const float* ln_b  = (const float*)d_in[2];
    const float* w_qkv = (const float*)d_in[3];
    const float* w_out = (const float*)d_in[4];
    float* out = (float*)d_out;

    rope_precompute_kernel<<<(JLEN * DH + 255) / 256, 256>>>();
    ln_kernel<<<M_ROWS, 256>>>(x, ln_g, ln_b);

    // qkv = xn @ w_qkv^T  (K=1024)
    gemm_mma<<<dim3(NT_N / 128, M_ROWS / 128), 256>>>(w_qkv, nullptr, DIM, 0);

    attn_kernel<<<dim3(NWIN, BATCH * HEADS), 256>>>();

    // out = attn @ w_out^T (K=512)
    gemm_mma<<<dim3(NT_N / 128, M_ROWS / 128), 256>>>(w_out, out, INNER, 1);
}